// round 13
// baseline (speedup 1.0000x reference)
#include <cuda_runtime.h>

#define N_NODES 100000
#define DIM 64
#define EPW 128        // edges per warp in aggregation
#define RPB 128        // rows per gemm block

// Scratch: aggY[i] = sum_{edges -> i} X[col].
// Zero-initialized at module load; gemm_kernel re-zeroes its slab at the END
// of each call, so "aggY == 0 on entry" holds for every call/replay.
__device__ float g_aggY[(size_t)N_NODES * DIM];

// ---------------------------------------------------------------------------
__device__ __forceinline__ unsigned long long fma2(unsigned long long a,
                                                   unsigned long long b,
                                                   unsigned long long c) {
    unsigned long long d;
    asm("fma.rn.f32x2 %0, %1, %2, %3;" : "=l"(d) : "l"(a), "l"(b), "l"(c));
    return d;
}
__device__ __forceinline__ float2 unpack2(unsigned long long p) {
    float lo, hi;
    asm("mov.b64 {%0,%1}, %2;" : "=f"(lo), "=f"(hi) : "l"(p));
    return make_float2(lo, hi);
}

// ---------------------------------------------------------------------------
// 1) edge aggregation: warp-segmented sum over sorted row_ids (unchanged).
// ---------------------------------------------------------------------------
__global__ __launch_bounds__(256) void agg_kernel(const float* __restrict__ X,
                                                  const int* __restrict__ rows,
                                                  const int* __restrict__ cols,
                                                  int E) {
    const unsigned full = 0xffffffffu;
    const int warp = (blockIdx.x * blockDim.x + threadIdx.x) >> 5;
    const int lane = threadIdx.x & 31;
    const int base = warp * EPW;
    if (base >= E) return;

    const float2* __restrict__ Xp = (const float2*)X;

    float ax = 0.f, ay = 0.f;
    int cur = __ldg(rows + base);

    if (base + EPW <= E) {
        int rm[4], cm[4];
#pragma unroll
        for (int g = 0; g < 4; g++) {
            rm[g] = __ldg(rows + base + g * 32 + lane);
            cm[g] = __ldg(cols + base + g * 32 + lane);
        }

        float2 v[2][8];
#pragma unroll
        for (int j = 0; j < 8; j++) {
            int ci = __shfl_sync(full, cm[0], j);
            v[0][j] = __ldg(Xp + (size_t)ci * 32 + lane);
        }

#pragma unroll
        for (int b = 0; b < 16; b++) {
            const int pb = b & 1, nb = pb ^ 1;
            if (b < 15) {
                const int g = (b + 1) >> 2, o = ((b + 1) & 3) * 8;
#pragma unroll
                for (int j = 0; j < 8; j++) {
                    int ci = __shfl_sync(full, cm[g], o + j);
                    v[nb][j] = __ldg(Xp + (size_t)ci * 32 + lane);
                }
            }
            const int g = b >> 2, o = (b & 3) * 8;
#pragma unroll
            for (int j = 0; j < 8; j++) {
                int ri = __shfl_sync(full, rm[g], o + j);
                if (ri != cur) {  // warp-uniform
                    float2* dst = (float2*)(g_aggY + (size_t)cur * DIM) + lane;
                    atomicAdd(dst, make_float2(ax, ay));
                    ax = 0.f; ay = 0.f;
                    cur = ri;
                }
                ax += v[pb][j].x;
                ay += v[pb][j].y;
            }
        }
    } else {
        int end = E;
        for (int e0 = base; e0 < end; e0 += 32) {
            int n = min(32, end - e0);
            int r = 0, c = 0;
            if (lane < n) {
                r = __ldg(rows + e0 + lane);
                c = __ldg(cols + e0 + lane);
            }
            for (int i = 0; i < n; i++) {
                int ri = __shfl_sync(full, r, i);
                int ci = __shfl_sync(full, c, i);
                if (ri != cur) {
                    float2* dst = (float2*)(g_aggY + (size_t)cur * DIM) + lane;
                    atomicAdd(dst, make_float2(ax, ay));
                    ax = 0.f; ay = 0.f;
                    cur = ri;
                }
                float2 v = __ldg(Xp + (size_t)ci * 32 + lane);
                ax += v.x;
                ay += v.y;
            }
        }
    }
    float2* dst = (float2*)(g_aggY + (size_t)cur * DIM) + lane;
    atomicAdd(dst, make_float2(ax, ay));
}

// ---------------------------------------------------------------------------
// 2) dual GEMM: out = (aggY/dd1) @ W + X @ W1, then re-zero aggY slab.
//    128 rows/block, 256 threads, 8x4 thread tile, k-pair FFMA2.
//    XY smem: float4 chunks (x2k, x2k+1, y2k, y2k+1), XOR-swizzled columns
//      (chunk col kp stored at kp ^ (((r>>3)&3)<<3)) -> conflict-free reads.
//    Weights: float4 = (W[2kp][c],W[2kp+1][c],W[2kp][c+1],W[2kp+1][c+1])
//      at Wg4[(kp*2+h)*16 + cq]  (h = col-pair within thread's 4 cols).
// ---------------------------------------------------------------------------
__global__ __launch_bounds__(256, 2) void gemm_kernel(
    const float* __restrict__ X,
    const float* __restrict__ W,
    const float* __restrict__ W1,
    const float* __restrict__ dd1,
    float* __restrict__ out,
    int N) {
    extern __shared__ float smem[];
    float4* XY  = (float4*)smem;            // [128][32] float4 = 64 KB
    float4* Wg4 = XY + RPB * 32;            // 1024 float4 = 16 KB
    float4* Qg4 = Wg4 + 1024;               // 1024 float4 = 16 KB

    const int tid  = threadIdx.x;
    const int row0 = blockIdx.x * RPB;

    // ---- pack weights: Wg4[(kp*2+h)*16 + cq].f[l*2+par] = W[2kp+par][4cq+2h+l]
    for (int i = tid; i < (DIM * DIM) / 4; i += 256) {
        int k   = i >> 4;            // 0..63
        int cq  = i & 15;            // col quad
        int kp  = k >> 1;
        int par = k & 1;
        float4 w = __ldg((const float4*)W + i);
        float4 u = __ldg((const float4*)W1 + i);
        float* wb = (float*)(Wg4 + (kp * 2) * 16 + cq) + par;
        float* qb = (float*)(Qg4 + (kp * 2) * 16 + cq) + par;
        // h=0: cols 4cq+0 (l=0), 4cq+1 (l=1); h=1 (+64 floats): cols +2, +3
        wb[0] = w.x;  wb[2] = w.y;  wb[64] = w.z;  wb[66] = w.w;
        qb[0] = u.x;  qb[2] = u.y;  qb[64] = u.z;  qb[66] = u.w;
    }

    // ---- load slabs: 2 threads per row, 8 float4s each ---------------------
    const float4 z4 = make_float4(0.f, 0.f, 0.f, 0.f);
    {
        int r    = tid >> 1;                 // 0..127
        int half = tid & 1;
        int row  = row0 + r;
        int sw   = ((r >> 3) & 3) << 3;
        float inv = 1.0f;
        if (row < N) inv = __frcp_rn(__ldg(dd1 + row));
#pragma unroll
        for (int jj = 0; jj < 8; jj++) {
            int j = half * 8 + jj;           // float4 index 0..15 (k = 4j..)
            float4 v = z4, u = z4;
            if (row < N) {
                v = __ldg((const float4*)(X + (size_t)row * DIM) + j);
                u = __ldg((const float4*)(g_aggY + (size_t)row * DIM) + j);
                u.x *= inv; u.y *= inv; u.z *= inv; u.w *= inv;
            }
            XY[r * 32 + ((2 * j) ^ sw)]     = make_float4(v.x, v.y, u.x, u.y);
            XY[r * 32 + ((2 * j + 1) ^ sw)] = make_float4(v.z, v.w, u.z, u.w);
        }
    }
    __syncthreads();

    const int cq = tid & 15;     // col quad 0..15  -> cols 4cq..4cq+3
    const int rq = tid >> 4;     // row group 0..15 -> rows 8rq..8rq+7
    const int sw = (rq & 3) << 3;
    const int rbase = rq * 8;

    unsigned long long acc[8][4];
#pragma unroll
    for (int i = 0; i < 8; i++)
#pragma unroll
        for (int j = 0; j < 4; j++) acc[i][j] = 0ull;

#pragma unroll 4
    for (int kp = 0; kp < 32; kp++) {
        ulonglong2 w0 = *(const ulonglong2*)(Wg4 + (kp * 2 + 0) * 16 + cq);
        ulonglong2 w1 = *(const ulonglong2*)(Wg4 + (kp * 2 + 1) * 16 + cq);
        ulonglong2 q0 = *(const ulonglong2*)(Qg4 + (kp * 2 + 0) * 16 + cq);
        ulonglong2 q1 = *(const ulonglong2*)(Qg4 + (kp * 2 + 1) * 16 + cq);
        const int kc = kp ^ sw;
#pragma unroll
        for (int i = 0; i < 8; i++) {
            ulonglong2 xy = *(const ulonglong2*)(XY + (rbase + i) * 32 + kc);
            // xy.x = (x2k, x2k+1), xy.y = (y2k, y2k+1)
            acc[i][0] = fma2(xy.y, w0.x, acc[i][0]);
            acc[i][1] = fma2(xy.y, w0.y, acc[i][1]);
            acc[i][2] = fma2(xy.y, w1.x, acc[i][2]);
            acc[i][3] = fma2(xy.y, w1.y, acc[i][3]);
            acc[i][0] = fma2(xy.x, q0.x, acc[i][0]);
            acc[i][1] = fma2(xy.x, q0.y, acc[i][1]);
            acc[i][2] = fma2(xy.x, q1.x, acc[i][2]);
            acc[i][3] = fma2(xy.x, q1.y, acc[i][3]);
        }
    }

#pragma unroll
    for (int i = 0; i < 8; i++) {
        int row = row0 + rbase + i;
        if (row < N) {
            float2 a0 = unpack2(acc[i][0]);
            float2 a1 = unpack2(acc[i][1]);
            float2 a2 = unpack2(acc[i][2]);
            float2 a3 = unpack2(acc[i][3]);
            ((float4*)(out + (size_t)row * DIM))[cq] =
                make_float4(a0.x + a0.y, a1.x + a1.y, a2.x + a2.y, a3.x + a3.y);
        }
    }

    // ---- re-zero our aggY slab for the next call/replay -------------------
    for (int idx = tid; idx < RPB * 16; idx += 256) {
        int row = row0 + (idx >> 4);
        if (row < N) {
            ((float4*)(g_aggY + (size_t)row * DIM))[idx & 15] = z4;
        }
    }
}

// ---------------------------------------------------------------------------
extern "C" void kernel_launch(void* const* d_in, const int* in_sizes, int n_in,
                              void* d_out, int out_size) {
    const float* X    = (const float*)d_in[0];   // [N, 64]
    const float* W    = (const float*)d_in[1];   // [64, 64]
    const float* W1   = (const float*)d_in[2];   // [64, 64]
    const float* dd1  = (const float*)d_in[3];   // [N, 1]
    const int*   rows = (const int*)d_in[4];     // [E] sorted
    const int*   cols = (const int*)d_in[5];     // [E]
    float*       out  = (float*)d_out;           // [N, 64]

    int N = in_sizes[0] / DIM;
    int E = in_sizes[4];

    // 1) edge aggregation into g_aggY (zero on entry; see gemm epilogue)
    {
        int nwarps  = (E + EPW - 1) / EPW;
        int nblocks = (nwarps + 7) / 8;
        agg_kernel<<<nblocks, 256>>>(X, rows, cols, E);
    }

    // 2) dual GEMM -> out (+ re-zero g_aggY at end)
    {
        int nblocks = (N + RPB - 1) / RPB;
        size_t smem_bytes = (RPB * 32 + 2 * 1024) * sizeof(float4);
        static int smem_set = 0;
        if (!smem_set) {
            cudaFuncSetAttribute(gemm_kernel,
                                 cudaFuncAttributeMaxDynamicSharedMemorySize,
                                 (int)smem_bytes);
            smem_set = 1;
        }
        gemm_kernel<<<nblocks, 256, smem_bytes>>>(X, W, W1, dd1, out, N);
    }
}

// round 14
// speedup vs baseline: 1.0656x; 1.0656x over previous
#include <cuda_runtime.h>

#define N_NODES 100000
#define DIM 64
#define EPW 128        // edges per warp in aggregation
#define P 66           // smem slab row pitch (floats)

// Scratch: aggY[i] = sum_{edges -> i} X[col].
// Zero-initialized at module load; kernel2 re-zeroes after consuming, so
// "aggY == 0 on entry" holds for every call/replay.
__device__ float g_aggY[(size_t)N_NODES * DIM];

typedef unsigned long long ull;

__device__ __forceinline__ ull fma2(ull a, ull b, ull c) {
    ull d;
    asm("fma.rn.f32x2 %0, %1, %2, %3;" : "=l"(d) : "l"(a), "l"(b), "l"(c));
    return d;
}
__device__ __forceinline__ float2 unpack2(ull p) {
    float lo, hi;
    asm("mov.b64 {%0,%1}, %2;" : "=f"(lo), "=f"(hi) : "l"(p));
    return make_float2(lo, hi);
}

// ---------------------------------------------------------------------------
// agg role: warp-segmented sum over sorted row_ids (proven, unchanged logic).
// ---------------------------------------------------------------------------
__device__ __forceinline__ void agg_role(const float* __restrict__ X,
                                         const int* __restrict__ rows,
                                         const int* __restrict__ cols,
                                         int E, int blk) {
    const unsigned full = 0xffffffffu;
    const int warp = (blk * 256 + (int)threadIdx.x) >> 5;
    const int lane = threadIdx.x & 31;
    const int base = warp * EPW;
    if (base >= E) return;

    const float2* __restrict__ Xp = (const float2*)X;

    float ax = 0.f, ay = 0.f;
    int cur = __ldg(rows + base);

    if (base + EPW <= E) {
        int rm[4], cm[4];
#pragma unroll
        for (int g = 0; g < 4; g++) {
            rm[g] = __ldg(rows + base + g * 32 + lane);
            cm[g] = __ldg(cols + base + g * 32 + lane);
        }

        float2 v[2][8];
#pragma unroll
        for (int j = 0; j < 8; j++) {
            int ci = __shfl_sync(full, cm[0], j);
            v[0][j] = __ldg(Xp + (size_t)ci * 32 + lane);
        }

#pragma unroll
        for (int b = 0; b < 16; b++) {
            const int pb = b & 1, nb = pb ^ 1;
            if (b < 15) {
                const int g = (b + 1) >> 2, o = ((b + 1) & 3) * 8;
#pragma unroll
                for (int j = 0; j < 8; j++) {
                    int ci = __shfl_sync(full, cm[g], o + j);
                    v[nb][j] = __ldg(Xp + (size_t)ci * 32 + lane);
                }
            }
            const int g = b >> 2, o = (b & 3) * 8;
#pragma unroll
            for (int j = 0; j < 8; j++) {
                int ri = __shfl_sync(full, rm[g], o + j);
                if (ri != cur) {  // warp-uniform
                    float2* dst = (float2*)(g_aggY + (size_t)cur * DIM) + lane;
                    atomicAdd(dst, make_float2(ax, ay));
                    ax = 0.f; ay = 0.f;
                    cur = ri;
                }
                ax += v[pb][j].x;
                ay += v[pb][j].y;
            }
        }
    } else {
        for (int e0 = base; e0 < E; e0 += 32) {
            int n = min(32, E - e0);
            int r = 0, c = 0;
            if (lane < n) {
                r = __ldg(rows + e0 + lane);
                c = __ldg(cols + e0 + lane);
            }
            for (int i = 0; i < n; i++) {
                int ri = __shfl_sync(full, r, i);
                int ci = __shfl_sync(full, c, i);
                if (ri != cur) {
                    float2* dst = (float2*)(g_aggY + (size_t)cur * DIM) + lane;
                    atomicAdd(dst, make_float2(ax, ay));
                    ax = 0.f; ay = 0.f;
                    cur = ri;
                }
                float2 v = __ldg(Xp + (size_t)ci * 32 + lane);
                ax += v.x;
                ay += v.y;
            }
        }
    }
    float2* dst = (float2*)(g_aggY + (size_t)cur * DIM) + lane;
    atomicAdd(dst, make_float2(ax, ay));
}

// ---------------------------------------------------------------------------
// conflict-free weight pack (R11-proven):
//   Wg[(kp*4+jj)*16 + q] (ull) = (M[2kp][4q+jj], M[2kp+1][4q+jj])
// ---------------------------------------------------------------------------
__device__ __forceinline__ void pack_weights(const float* __restrict__ M,
                                             float* Wg) {
    for (int i = threadIdx.x; i < (DIM * DIM) / 4; i += 256) {
        int k   = i >> 4;
        int q   = i & 15;
        int kp  = k >> 1;
        int par = k & 1;
        float4 w = __ldg((const float4*)M + i);
        int b0 = 2 * (kp * 64 + q) + par;
        Wg[b0 + 0]  = w.x; Wg[b0 + 32] = w.y;
        Wg[b0 + 64] = w.z; Wg[b0 + 96] = w.w;
    }
}

// ---------------------------------------------------------------------------
// Kernel 1: heterogeneous grid.
//   blocks [0, nAgg)          : agg role -> g_aggY
//   blocks [nAgg, nAgg+nGemm) : out = X @ W1   (independent of agg)
// ---------------------------------------------------------------------------
__global__ __launch_bounds__(256) void fused1_kernel(
    const float* __restrict__ X,
    const float* __restrict__ W1,
    const int* __restrict__ rows,
    const int* __restrict__ cols,
    float* __restrict__ out,
    int N, int E, int nAgg) {
    extern __shared__ float smem[];

    if ((int)blockIdx.x < nAgg) {
        agg_role(X, rows, cols, E, blockIdx.x);
        return;
    }

    float* Xs = smem;            // [64][P]
    float* Wg = Xs + 64 * P;     // packed 4096 floats

    const int tid  = threadIdx.x;
    const int row0 = ((int)blockIdx.x - nAgg) * 64;

    pack_weights(W1, Wg);

    const float4 z4 = make_float4(0.f, 0.f, 0.f, 0.f);
    for (int idx = tid; idx < 64 * 16; idx += 256) {
        int r   = idx >> 4;
        int k4  = (idx & 15) * 4;
        int row = row0 + r;
        float4 v = z4;
        if (row < N) v = __ldg((const float4*)(X + (size_t)row * DIM + k4));
        float* xr = Xs + r * P + k4;
        xr[0] = v.x; xr[1] = v.y; xr[2] = v.z; xr[3] = v.w;
    }
    __syncthreads();

    const int cq = tid & 15;
    const int rq = tid >> 4;
    const int rt = rq * 4;
    const int c0 = cq * 4;

    ull acc[4][4];
#pragma unroll
    for (int i = 0; i < 4; i++)
#pragma unroll
        for (int j = 0; j < 4; j++) acc[i][j] = 0ull;

    const ull* Wq = (const ull*)Wg + cq;

#pragma unroll 8
    for (int kp = 0; kp < 32; kp++) {
        ull w0 = Wq[(kp * 4 + 0) * 16];
        ull w1 = Wq[(kp * 4 + 1) * 16];
        ull w2 = Wq[(kp * 4 + 2) * 16];
        ull w3 = Wq[(kp * 4 + 3) * 16];
#pragma unroll
        for (int i = 0; i < 4; i++) {
            ull xp = *(const ull*)(Xs + (rt + i) * P + 2 * kp);
            acc[i][0] = fma2(xp, w0, acc[i][0]);
            acc[i][1] = fma2(xp, w1, acc[i][1]);
            acc[i][2] = fma2(xp, w2, acc[i][2]);
            acc[i][3] = fma2(xp, w3, acc[i][3]);
        }
    }

#pragma unroll
    for (int i = 0; i < 4; i++) {
        int row = row0 + rt + i;
        if (row < N) {
            float2 a0 = unpack2(acc[i][0]);
            float2 a1 = unpack2(acc[i][1]);
            float2 a2 = unpack2(acc[i][2]);
            float2 a3 = unpack2(acc[i][3]);
            *(float4*)(out + (size_t)row * DIM + c0) =
                make_float4(a0.x + a0.y, a1.x + a1.y, a2.x + a2.y, a3.x + a3.y);
        }
    }
}

// ---------------------------------------------------------------------------
// Kernel 2: out += (aggY/dd1) @ W ; re-zero aggY slab in epilogue.
// ---------------------------------------------------------------------------
__global__ __launch_bounds__(256) void gemm2_kernel(
    const float* __restrict__ W,
    const float* __restrict__ dd1,
    float* __restrict__ out,
    int N) {
    extern __shared__ float smem[];
    float* Ys = smem;            // [64][P]
    float* Wg = Ys + 64 * P;     // packed 4096 floats

    const int tid  = threadIdx.x;
    const int row0 = blockIdx.x * 64;

    pack_weights(W, Wg);

    const float4 z4 = make_float4(0.f, 0.f, 0.f, 0.f);
    for (int idx = tid; idx < 64 * 16; idx += 256) {
        int r   = idx >> 4;
        int k4  = (idx & 15) * 4;
        int row = row0 + r;
        float4 u = z4;
        if (row < N) {
            u = __ldg((const float4*)(g_aggY + (size_t)row * DIM + k4));
            float inv = __frcp_rn(__ldg(dd1 + row));
            u.x *= inv; u.y *= inv; u.z *= inv; u.w *= inv;
        }
        float* yr = Ys + r * P + k4;
        yr[0] = u.x; yr[1] = u.y; yr[2] = u.z; yr[3] = u.w;
    }
    __syncthreads();

    const int cq = tid & 15;
    const int rq = tid >> 4;
    const int rt = rq * 4;
    const int c0 = cq * 4;

    ull acc[4][4];
#pragma unroll
    for (int i = 0; i < 4; i++)
#pragma unroll
        for (int j = 0; j < 4; j++) acc[i][j] = 0ull;

    const ull* Wq = (const ull*)Wg + cq;

#pragma unroll 8
    for (int kp = 0; kp < 32; kp++) {
        ull w0 = Wq[(kp * 4 + 0) * 16];
        ull w1 = Wq[(kp * 4 + 1) * 16];
        ull w2 = Wq[(kp * 4 + 2) * 16];
        ull w3 = Wq[(kp * 4 + 3) * 16];
#pragma unroll
        for (int i = 0; i < 4; i++) {
            ull yp = *(const ull*)(Ys + (rt + i) * P + 2 * kp);
            acc[i][0] = fma2(yp, w0, acc[i][0]);
            acc[i][1] = fma2(yp, w1, acc[i][1]);
            acc[i][2] = fma2(yp, w2, acc[i][2]);
            acc[i][3] = fma2(yp, w3, acc[i][3]);
        }
    }

#pragma unroll
    for (int i = 0; i < 4; i++) {
        int row = row0 + rt + i;
        if (row < N) {
            float4 o = *(const float4*)(out + (size_t)row * DIM + c0);
            float2 a0 = unpack2(acc[i][0]);
            float2 a1 = unpack2(acc[i][1]);
            float2 a2 = unpack2(acc[i][2]);
            float2 a3 = unpack2(acc[i][3]);
            o.x += a0.x + a0.y;
            o.y += a1.x + a1.y;
            o.z += a2.x + a2.y;
            o.w += a3.x + a3.y;
            *(float4*)(out + (size_t)row * DIM + c0) = o;
        }
    }

    // re-zero our aggY slab for the next call/replay
    for (int idx = tid; idx < 64 * 16; idx += 256) {
        int row = row0 + (idx >> 4);
        if (row < N) {
            ((float4*)(g_aggY + (size_t)row * DIM))[idx & 15] = z4;
        }
    }
}

// ---------------------------------------------------------------------------
extern "C" void kernel_launch(void* const* d_in, const int* in_sizes, int n_in,
                              void* d_out, int out_size) {
    const float* X    = (const float*)d_in[0];   // [N, 64]
    const float* W    = (const float*)d_in[1];   // [64, 64]
    const float* W1   = (const float*)d_in[2];   // [64, 64]
    const float* dd1  = (const float*)d_in[3];   // [N, 1]
    const int*   rows = (const int*)d_in[4];     // [E] sorted
    const int*   cols = (const int*)d_in[5];     // [E]
    float*       out  = (float*)d_out;           // [N, 64]

    int N = in_sizes[0] / DIM;
    int E = in_sizes[4];

    int nAgg  = ((E + EPW - 1) / EPW + 7) / 8;   // agg blocks (8 warps each)
    int nGemm = (N + 63) / 64;                   // 64-row gemm blocks
    size_t smem_bytes = (64 * P + DIM * DIM) * sizeof(float);   // 33 KB

    // 1) agg -> g_aggY  ||  out = X @ W1   (one heterogeneous grid)
    fused1_kernel<<<nAgg + nGemm, 256, smem_bytes>>>(
        X, W1, rows, cols, out, N, E, nAgg);

    // 2) out += (aggY/dd1) @ W ; re-zero aggY
    gemm2_kernel<<<nGemm, 256, smem_bytes>>>(W, dd1, out, N);
}